// round 4
// baseline (speedup 1.0000x reference)
#include <cuda_runtime.h>
#include <math.h>

// Problem constants (fixed by the dataset instance)
#define BATCH   8
#define NP      4096
#define FDIM    512
#define H1DIM   256
#define H2DIM   128
#define DDIM    6

#define FSCORE_W 0.1f
#define TASK_W   1.0f
#define DOMAIN_W 0.1f
#define INV_C    5000.0f       // 1/(2*sigma^2)

// Chamfer tiling: each block owns 128 queries and scans ALL 4096 keys.
#define TPB     128
#define QB      (NP/TPB)       // 32 query-blocks per (batch, direction)
#define KTILE   128            // keys per shared tile

// Scratch (device globals: no allocation allowed).
// g_part[dir][b][qblock][0] = sum of min dists, [1] = sum of exp terms.
// Every slot is written unconditionally every launch -> no init needed.
__device__ float g_part[2][BATCH][QB][2];
__device__ float g_dom[BATCH];

// ---------------- f32x2 helpers (sm_100+ packed fp32) ----------------
__device__ __forceinline__ unsigned long long pack2(float lo, float hi) {
    unsigned long long r;
    asm("mov.b64 %0, {%1, %2};" : "=l"(r) : "f"(lo), "f"(hi));
    return r;
}
__device__ __forceinline__ unsigned long long fma2(unsigned long long a,
                                                   unsigned long long b,
                                                   unsigned long long c) {
    unsigned long long r;
    asm("fma.rn.f32x2 %0, %1, %2, %3;" : "=l"(r) : "l"(a), "l"(b), "l"(c));
    return r;
}
__device__ __forceinline__ float2 unpack2(unsigned long long v) {
    float2 f;
    asm("mov.b64 {%0, %1}, %2;" : "=f"(f.x), "=f"(f.y) : "l"(v));
    return f;
}

// One direction of chamfer per blockIdx.y: dir 0 = pred->target (row mins),
// dir 1 = target->pred. Each thread owns ONE query, register-min over all
// 4096 keys (two keys per packed FFMA2 chain), then the block reduces its
// 128 finished mins to (sum_d, sum_exp) partials. No atomics anywhere.
__global__ __launch_bounds__(TPB) void chamfer_kernel(
    const float* __restrict__ P, const float* __restrict__ T)
{
    const int dir = blockIdx.y;
    const int b   = blockIdx.z;
    const int qb  = blockIdx.x;
    const int tid = threadIdx.x;

    const float* Q = dir ? (T + (size_t)b * NP * 3) : (P + (size_t)b * NP * 3);
    const float* K = dir ? (P + (size_t)b * NP * 3) : (T + (size_t)b * NP * 3);

    // skA[j].x = {-2x_{2j}, -2x_{2j+1}}   skA[j].y = {-2y pair}
    // skB[j].x = {-2z pair}               skB[j].y = {|k|^2 pair}
    __shared__ ulonglong2 skA[KTILE / 2];
    __shared__ ulonglong2 skB[KTILE / 2];

    const int q = qb * TPB + tid;
    const float qx = Q[q * 3 + 0];
    const float qy = Q[q * 3 + 1];
    const float qz = Q[q * 3 + 2];
    const unsigned long long qxd = pack2(qx, qx);
    const unsigned long long qyd = pack2(qy, qy);
    const unsigned long long qzd = pack2(qz, qz);
    const float q2 = qx * qx + qy * qy + qz * qz;
    float emin = __int_as_float(0x7f800000);

    for (int kt = 0; kt < NP; kt += KTILE) {
        __syncthreads();
        if (tid < KTILE / 2) {
            int k = kt + 2 * tid;
            float kx0 = K[k * 3 + 0], ky0 = K[k * 3 + 1], kz0 = K[k * 3 + 2];
            float kx1 = K[k * 3 + 3], ky1 = K[k * 3 + 4], kz1 = K[k * 3 + 5];
            ulonglong2 A, B;
            A.x = pack2(-2.0f * kx0, -2.0f * kx1);
            A.y = pack2(-2.0f * ky0, -2.0f * ky1);
            B.x = pack2(-2.0f * kz0, -2.0f * kz1);
            B.y = pack2(kx0 * kx0 + ky0 * ky0 + kz0 * kz0,
                        kx1 * kx1 + ky1 * ky1 + kz1 * kz1);
            skA[tid] = A;
            skB[tid] = B;
        }
        __syncthreads();

        #pragma unroll 8
        for (int j = 0; j < KTILE / 2; j++) {
            ulonglong2 A = skA[j];   // LDS.128 warp-uniform broadcast
            ulonglong2 B = skB[j];
            unsigned long long e = fma2(qxd, A.x, B.y);
            e = fma2(qyd, A.y, e);
            e = fma2(qzd, B.x, e);
            float2 ef = unpack2(e);
            emin = fminf(emin, fminf(ef.x, ef.y));
        }
    }

    // Finished min for this query: fold q2, compute soft term, block-reduce.
    float d  = emin + q2;
    float ex = __expf(-d * INV_C);

    #pragma unroll
    for (int s = 16; s > 0; s >>= 1) {
        d  += __shfl_xor_sync(0xffffffffu, d,  s);
        ex += __shfl_xor_sync(0xffffffffu, ex, s);
    }
    __shared__ float red[4][2];
    if ((tid & 31) == 0) {
        red[tid >> 5][0] = d;
        red[tid >> 5][1] = ex;
    }
    __syncthreads();
    if (tid == 0) {
        float sd = red[0][0] + red[1][0] + red[2][0] + red[3][0];
        float se = red[0][1] + red[1][1] + red[2][1] + red[3][1];
        g_part[dir][b][qb][0] = sd;
        g_part[dir][b][qb][1] = se;
    }
}

// Domain classifier: 512 -> relu 256 -> relu 128 -> 6 logits -> NLL per batch.
// 512 threads: each layer splits its K-dimension in half across thread pairs
// to halve the serial FMA/load chain.
__global__ __launch_bounds__(512) void domain_kernel(
    const float* __restrict__ X,
    const float* __restrict__ W1, const float* __restrict__ b1,
    const float* __restrict__ W2, const float* __restrict__ b2,
    const float* __restrict__ W3, const float* __restrict__ b3,
    const int* __restrict__ labels)
{
    const int b = blockIdx.x;
    const int tid = threadIdx.x;
    __shared__ float xs[FDIM];
    __shared__ float part1[2 * H1DIM];
    __shared__ float h1[H1DIM];
    __shared__ float part2[2 * H2DIM];
    __shared__ float h2[H2DIM];
    __shared__ float lg[DDIM];

    if (tid < FDIM) xs[tid] = X[b * FDIM + tid];
    __syncthreads();

    {   // layer 1: 256 outputs x 2 k-halves (256 each)
        int out  = tid & (H1DIM - 1);
        int half = tid >> 8;            // 0 or 1
        int f0 = half * (FDIM / 2);
        float a = 0.0f;
        #pragma unroll 8
        for (int f = 0; f < FDIM / 2; f++)
            a = fmaf(xs[f0 + f], W1[(f0 + f) * H1DIM + out], a);
        part1[half * H1DIM + out] = a;
    }
    __syncthreads();
    if (tid < H1DIM)
        h1[tid] = fmaxf(part1[tid] + part1[H1DIM + tid] + b1[tid], 0.0f);
    __syncthreads();

    if (tid < 2 * H2DIM) {   // layer 2: 128 outputs x 2 k-halves (128 each)
        int out  = tid & (H2DIM - 1);
        int half = tid >> 7;
        int k0 = half * (H1DIM / 2);
        float a = 0.0f;
        #pragma unroll 8
        for (int k = 0; k < H1DIM / 2; k++)
            a = fmaf(h1[k0 + k], W2[(k0 + k) * H2DIM + out], a);
        part2[half * H2DIM + out] = a;
    }
    __syncthreads();
    if (tid < H2DIM)
        h2[tid] = fmaxf(part2[tid] + part2[H2DIM + tid] + b2[tid], 0.0f);
    __syncthreads();

    if (tid < DDIM) {   // layer 3: 6 outputs x 128
        float a = b3[tid];
        #pragma unroll 8
        for (int k = 0; k < H2DIM; k++)
            a = fmaf(h2[k], W3[k * DDIM + tid], a);
        lg[tid] = a;
    }
    __syncthreads();
    if (tid == 0) {
        float mx = lg[0];
        for (int d = 1; d < DDIM; d++) mx = fmaxf(mx, lg[d]);
        float se = 0.f;
        for (int d = 0; d < DDIM; d++) se += expf(lg[d] - mx);
        g_dom[b] = (mx + logf(se)) - lg[labels[b]];
    }
}

// Final combine: one warp. Lanes 0..7 each own a batch: gather the 32
// qblock partials per direction, compute per-sample loss, then lane-reduce
// for the batch-level terms.
__global__ void combine_kernel(const float* __restrict__ dsw, float* __restrict__ out) {
    const int t = threadIdx.x;   // 32 threads
    float sA = 0.f, sEA = 0.f, sB = 0.f, sEB = 0.f;
    float dwc = 0.f, domc = 0.f;
    if (t < BATCH) {
        #pragma unroll 8
        for (int qb = 0; qb < QB; qb++) {
            sA  += g_part[0][t][qb][0];
            sEA += g_part[0][t][qb][1];
            sB  += g_part[1][t][qb][0];
            sEB += g_part[1][t][qb][1];
        }
        const float invN = 1.0f / (float)NP;
        float ch_i = sA * invN + sB * invN;
        float p_i  = sEA * invN;
        float r_i  = sEB * invN;
        float f_i  = 2.0f * p_i * r_i / (p_i + r_i + 1e-8f);
        float loss_i = ch_i + FSCORE_W * (1.0f - f_i);
        dwc  = dsw[t] * loss_i;
        domc = g_dom[t];
    }
    // reduce over the 8 active lanes (others contribute zeros)
    #pragma unroll
    for (int s = 16; s > 0; s >>= 1) {
        sA   += __shfl_xor_sync(0xffffffffu, sA,   s);
        sEA  += __shfl_xor_sync(0xffffffffu, sEA,  s);
        sB   += __shfl_xor_sync(0xffffffffu, sB,   s);
        sEB  += __shfl_xor_sync(0xffffffffu, sEB,  s);
        dwc  += __shfl_xor_sync(0xffffffffu, dwc,  s);
        domc += __shfl_xor_sync(0xffffffffu, domc, s);
    }
    if (t == 0) {
        const float invBN = 1.0f / (float)(BATCH * NP);
        float chamfer = sA * invBN + sB * invBN;
        float prec = sEA * invBN;
        float rec  = sEB * invBN;
        float fscore = 2.0f * prec * rec / (prec + rec + 1e-8f);
        float task = chamfer + FSCORE_W * (1.0f - fscore);
        out[0] = TASK_W * task + DOMAIN_W * (domc / (float)BATCH)
               + (dwc / (float)BATCH);
    }
}

extern "C" void kernel_launch(void* const* d_in, const int* in_sizes, int n_in,
                              void* d_out, int out_size)
{
    const float* pred_pc   = (const float*)d_in[0];
    const float* target_pc = (const float*)d_in[1];
    const float* dfeat     = (const float*)d_in[2];
    const float* dsw       = (const float*)d_in[3];
    const float* W1 = (const float*)d_in[4];
    const float* b1 = (const float*)d_in[5];
    const float* W2 = (const float*)d_in[6];
    const float* b2 = (const float*)d_in[7];
    const float* W3 = (const float*)d_in[8];
    const float* b3 = (const float*)d_in[9];
    const int*   labels = (const int*)d_in[10];
    float* out = (float*)d_out;

    dim3 grid(QB, 2, BATCH);   // (32, 2, 8) = 512 blocks, both directions
    chamfer_kernel<<<grid, TPB>>>(pred_pc, target_pc);
    domain_kernel<<<BATCH, 512>>>(dfeat, W1, b1, W2, b2, W3, b3, labels);
    combine_kernel<<<1, 32>>>(dsw, out);
}

// round 5
// speedup vs baseline: 1.6475x; 1.6475x over previous
#include <cuda_runtime.h>
#include <math.h>

// Problem constants (fixed by the dataset instance)
#define BATCH   8
#define NP      4096
#define FDIM    512
#define H1DIM   256
#define H2DIM   128
#define DDIM    6

#define FSCORE_W 0.1f
#define TASK_W   1.0f
#define DOMAIN_W 0.1f
#define INV_C    5000.0f       // 1/(2*sigma^2)

// Chamfer tiling
#define TPB     128
#define PPT     4
#define QTILE   (TPB*PPT)      // 512 queries per block
#define QB      (NP/QTILE)     // 8
#define KSPLIT  4
#define KCHUNK  (NP/KSPLIT)    // 1024 keys per block
#define KTILE   128            // keys per shared tile

#define RCHUNKS 4              // reduce kernel x-dim (1024 queries each)

// Scratch (device globals; every slot written unconditionally -> no init).
__device__ float g_pmin[2][BATCH][KSPLIT][NP];   // per-split partial mins
__device__ float g_r2[BATCH][RCHUNKS][4];        // per-chunk sA,sEA,sB,sEB
__device__ float g_dom[BATCH];

// ---------------- f32x2 helpers (sm_100+ packed fp32) ----------------
__device__ __forceinline__ unsigned long long pack2(float lo, float hi) {
    unsigned long long r;
    asm("mov.b64 %0, {%1, %2};" : "=l"(r) : "f"(lo), "f"(hi));
    return r;
}
__device__ __forceinline__ unsigned long long fma2(unsigned long long a,
                                                   unsigned long long b,
                                                   unsigned long long c) {
    unsigned long long r;
    asm("fma.rn.f32x2 %0, %1, %2, %3;" : "=l"(r) : "l"(a), "l"(b), "l"(c));
    return r;
}
__device__ __forceinline__ float2 unpack2(unsigned long long v) {
    float2 f;
    asm("mov.b64 {%0, %1}, %2;" : "=f"(f.x), "=f"(f.y) : "l"(v));
    return f;
}

// Both chamfer directions in one launch. blockIdx.y encodes (split, dir).
// Each thread owns PPT=4 queries, register-min over its 1024-key chunk
// (two keys per packed FFMA2 chain), then stores its partial mins to a
// UNIQUE g_pmin slice. No atomics, no init required.
__global__ __launch_bounds__(TPB) void chamfer_kernel(
    const float* __restrict__ P, const float* __restrict__ T)
{
    const int dir   = blockIdx.y & 1;
    const int split = blockIdx.y >> 1;
    const int b     = blockIdx.z;
    const int qb    = blockIdx.x;
    const int tid   = threadIdx.x;
    const int k0    = split * KCHUNK;

    const float* Q = dir ? (T + (size_t)b * NP * 3) : (P + (size_t)b * NP * 3);
    const float* K = dir ? (P + (size_t)b * NP * 3) : (T + (size_t)b * NP * 3);

    // skA[j].x = {-2x_{2j}, -2x_{2j+1}}   skA[j].y = {-2y pair}
    // skB[j].x = {-2z pair}               skB[j].y = {|k|^2 pair}
    __shared__ ulonglong2 skA[KTILE / 2];
    __shared__ ulonglong2 skB[KTILE / 2];

    unsigned long long qxd[PPT], qyd[PPT], qzd[PPT];
    float q2[PPT], emin[PPT];
    #pragma unroll
    for (int p = 0; p < PPT; p++) {
        int q = qb * QTILE + p * TPB + tid;
        float qx = Q[q * 3 + 0];
        float qy = Q[q * 3 + 1];
        float qz = Q[q * 3 + 2];
        qxd[p] = pack2(qx, qx);
        qyd[p] = pack2(qy, qy);
        qzd[p] = pack2(qz, qz);
        q2[p]  = qx * qx + qy * qy + qz * qz;
        emin[p] = __int_as_float(0x7f800000);
    }

    for (int kt = 0; kt < KCHUNK; kt += KTILE) {
        __syncthreads();
        if (tid < KTILE / 2) {
            int k = k0 + kt + 2 * tid;
            float kx0 = K[k * 3 + 0], ky0 = K[k * 3 + 1], kz0 = K[k * 3 + 2];
            float kx1 = K[k * 3 + 3], ky1 = K[k * 3 + 4], kz1 = K[k * 3 + 5];
            ulonglong2 A, B;
            A.x = pack2(-2.0f * kx0, -2.0f * kx1);
            A.y = pack2(-2.0f * ky0, -2.0f * ky1);
            B.x = pack2(-2.0f * kz0, -2.0f * kz1);
            B.y = pack2(kx0 * kx0 + ky0 * ky0 + kz0 * kz0,
                        kx1 * kx1 + ky1 * ky1 + kz1 * kz1);
            skA[tid] = A;
            skB[tid] = B;
        }
        __syncthreads();

        #pragma unroll 8
        for (int j = 0; j < KTILE / 2; j++) {
            ulonglong2 A = skA[j];   // LDS.128 warp-uniform broadcast
            ulonglong2 B = skB[j];   // LDS.128
            #pragma unroll
            for (int p = 0; p < PPT; p++) {
                unsigned long long e = fma2(qxd[p], A.x, B.y);
                e = fma2(qyd[p], A.y, e);
                e = fma2(qzd[p], B.x, e);
                float2 ef = unpack2(e);
                emin[p] = fminf(emin[p], fminf(ef.x, ef.y));
            }
        }
    }

    #pragma unroll
    for (int p = 0; p < PPT; p++) {
        int q = qb * QTILE + p * TPB + tid;   // coalesced unique store
        g_pmin[dir][b][split][q] = emin[p] + q2[p];
    }
}

// Min over the KSPLIT partials, then per-batch sums of min dists and soft
// exp terms for both directions. Unique g_r2 slot per block -> no atomics.
__global__ __launch_bounds__(256) void reduce_kernel() {
    const int b   = blockIdx.y;
    const int tid = threadIdx.x;
    const int q0  = blockIdx.x * 1024 + tid * 4;

    float sums[4];   // sA, sEA, sB, sEB
    #pragma unroll
    for (int dir = 0; dir < 2; dir++) {
        const float4* s0 = (const float4*)&g_pmin[dir][b][0][q0];
        const float4* s1 = (const float4*)&g_pmin[dir][b][1][q0];
        const float4* s2 = (const float4*)&g_pmin[dir][b][2][q0];
        const float4* s3 = (const float4*)&g_pmin[dir][b][3][q0];
        float4 a = *s0, c = *s1, d = *s2, e = *s3;
        float m0 = fminf(fminf(a.x, c.x), fminf(d.x, e.x));
        float m1 = fminf(fminf(a.y, c.y), fminf(d.y, e.y));
        float m2 = fminf(fminf(a.z, c.z), fminf(d.z, e.z));
        float m3 = fminf(fminf(a.w, c.w), fminf(d.w, e.w));
        sums[dir * 2 + 0] = m0 + m1 + m2 + m3;
        sums[dir * 2 + 1] = __expf(-m0 * INV_C) + __expf(-m1 * INV_C)
                          + __expf(-m2 * INV_C) + __expf(-m3 * INV_C);
    }

    #pragma unroll
    for (int s = 16; s > 0; s >>= 1) {
        #pragma unroll
        for (int i = 0; i < 4; i++)
            sums[i] += __shfl_xor_sync(0xffffffffu, sums[i], s);
    }

    __shared__ float red[8][4];
    int w = tid >> 5;
    if ((tid & 31) == 0) {
        red[w][0] = sums[0]; red[w][1] = sums[1];
        red[w][2] = sums[2]; red[w][3] = sums[3];
    }
    __syncthreads();
    if (tid < 4) {
        float acc = 0.f;
        #pragma unroll
        for (int ww = 0; ww < 8; ww++) acc += red[ww][tid];
        g_r2[b][blockIdx.x][tid] = acc;
    }
}

// Domain classifier: 512 -> relu 256 -> relu 128 -> 6 logits -> NLL per batch.
// 512 threads; each layer splits its K-dimension in half to shorten chains.
__global__ __launch_bounds__(512) void domain_kernel(
    const float* __restrict__ X,
    const float* __restrict__ W1, const float* __restrict__ b1,
    const float* __restrict__ W2, const float* __restrict__ b2,
    const float* __restrict__ W3, const float* __restrict__ b3,
    const int* __restrict__ labels)
{
    const int b = blockIdx.x;
    const int tid = threadIdx.x;
    __shared__ float xs[FDIM];
    __shared__ float part1[2 * H1DIM];
    __shared__ float h1[H1DIM];
    __shared__ float part2[2 * H2DIM];
    __shared__ float h2[H2DIM];
    __shared__ float lg[DDIM];

    if (tid < FDIM) xs[tid] = X[b * FDIM + tid];
    __syncthreads();

    {   // layer 1: 256 outputs x 2 k-halves
        int out  = tid & (H1DIM - 1);
        int half = tid >> 8;
        int f0 = half * (FDIM / 2);
        float a = 0.0f;
        #pragma unroll 8
        for (int f = 0; f < FDIM / 2; f++)
            a = fmaf(xs[f0 + f], W1[(f0 + f) * H1DIM + out], a);
        part1[half * H1DIM + out] = a;
    }
    __syncthreads();
    if (tid < H1DIM)
        h1[tid] = fmaxf(part1[tid] + part1[H1DIM + tid] + b1[tid], 0.0f);
    __syncthreads();

    if (tid < 2 * H2DIM) {   // layer 2: 128 outputs x 2 k-halves
        int out  = tid & (H2DIM - 1);
        int half = tid >> 7;
        int k0 = half * (H1DIM / 2);
        float a = 0.0f;
        #pragma unroll 8
        for (int k = 0; k < H1DIM / 2; k++)
            a = fmaf(h1[k0 + k], W2[(k0 + k) * H2DIM + out], a);
        part2[half * H2DIM + out] = a;
    }
    __syncthreads();
    if (tid < H2DIM)
        h2[tid] = fmaxf(part2[tid] + part2[H2DIM + tid] + b2[tid], 0.0f);
    __syncthreads();

    if (tid < DDIM) {   // layer 3: 6 outputs x 128
        float a = b3[tid];
        #pragma unroll 8
        for (int k = 0; k < H2DIM; k++)
            a = fmaf(h2[k], W3[k * DDIM + tid], a);
        lg[tid] = a;
    }
    __syncthreads();
    if (tid == 0) {
        float mx = lg[0];
        for (int d = 1; d < DDIM; d++) mx = fmaxf(mx, lg[d]);
        float se = 0.f;
        for (int d = 0; d < DDIM; d++) se += expf(lg[d] - mx);
        g_dom[b] = (mx + logf(se)) - lg[labels[b]];
    }
}

// Final combine: one warp; lanes 0..7 each own a batch.
__global__ void combine_kernel(const float* __restrict__ dsw, float* __restrict__ out) {
    const int t = threadIdx.x;
    float sA = 0.f, sEA = 0.f, sB = 0.f, sEB = 0.f;
    float dwc = 0.f, domc = 0.f;
    if (t < BATCH) {
        #pragma unroll
        for (int c = 0; c < RCHUNKS; c++) {
            sA  += g_r2[t][c][0];
            sEA += g_r2[t][c][1];
            sB  += g_r2[t][c][2];
            sEB += g_r2[t][c][3];
        }
        const float invN = 1.0f / (float)NP;
        float ch_i = sA * invN + sB * invN;
        float p_i  = sEA * invN;
        float r_i  = sEB * invN;
        float f_i  = 2.0f * p_i * r_i / (p_i + r_i + 1e-8f);
        float loss_i = ch_i + FSCORE_W * (1.0f - f_i);
        dwc  = dsw[t] * loss_i;
        domc = g_dom[t];
    }
    #pragma unroll
    for (int s = 16; s > 0; s >>= 1) {
        sA   += __shfl_xor_sync(0xffffffffu, sA,   s);
        sEA  += __shfl_xor_sync(0xffffffffu, sEA,  s);
        sB   += __shfl_xor_sync(0xffffffffu, sB,   s);
        sEB  += __shfl_xor_sync(0xffffffffu, sEB,  s);
        dwc  += __shfl_xor_sync(0xffffffffu, dwc,  s);
        domc += __shfl_xor_sync(0xffffffffu, domc, s);
    }
    if (t == 0) {
        const float invBN = 1.0f / (float)(BATCH * NP);
        float chamfer = sA * invBN + sB * invBN;
        float prec = sEA * invBN;
        float rec  = sEB * invBN;
        float fscore = 2.0f * prec * rec / (prec + rec + 1e-8f);
        float task = chamfer + FSCORE_W * (1.0f - fscore);
        out[0] = TASK_W * task + DOMAIN_W * (domc / (float)BATCH)
               + (dwc / (float)BATCH);
    }
}

extern "C" void kernel_launch(void* const* d_in, const int* in_sizes, int n_in,
                              void* d_out, int out_size)
{
    const float* pred_pc   = (const float*)d_in[0];
    const float* target_pc = (const float*)d_in[1];
    const float* dfeat     = (const float*)d_in[2];
    const float* dsw       = (const float*)d_in[3];
    const float* W1 = (const float*)d_in[4];
    const float* b1 = (const float*)d_in[5];
    const float* W2 = (const float*)d_in[6];
    const float* b2 = (const float*)d_in[7];
    const float* W3 = (const float*)d_in[8];
    const float* b3 = (const float*)d_in[9];
    const int*   labels = (const int*)d_in[10];
    float* out = (float*)d_out;

    dim3 grid(QB, 2 * KSPLIT, BATCH);   // (8, 8, 8) = 512 blocks
    chamfer_kernel<<<grid, TPB>>>(pred_pc, target_pc);

    dim3 rgrid(RCHUNKS, BATCH);
    reduce_kernel<<<rgrid, 256>>>();
    domain_kernel<<<BATCH, 512>>>(dfeat, W1, b1, W2, b2, W3, b3, labels);
    combine_kernel<<<1, 32>>>(dsw, out);
}

// round 6
// speedup vs baseline: 1.8987x; 1.1525x over previous
#include <cuda_runtime.h>
#include <math.h>

// Problem constants (fixed by the dataset instance)
#define BATCH   8
#define NP      4096
#define FDIM    512
#define H1DIM   256
#define H2DIM   128
#define DDIM    6

#define FSCORE_W 0.1f
#define TASK_W   1.0f
#define DOMAIN_W 0.1f
#define INV_C    5000.0f       // 1/(2*sigma^2)

// Chamfer tiling
#define TPB     128
#define PPT     4
#define QTILE   (TPB*PPT)      // 512 queries per block
#define QB      (NP/QTILE)     // 8
#define KSPLIT  4
#define KCHUNK  (NP/KSPLIT)    // 1024 keys per block
#define KTILE   128            // keys per shared tile
#define NTILES  (KCHUNK/KTILE) // 8

#define RCHUNKS 4              // reduce kernel x-dim (1024 queries each)

// Scratch (device globals; every data slot written unconditionally -> no init).
__device__ float g_pmin[2][BATCH][KSPLIT][NP];   // per-split partial mins
__device__ float g_r2[BATCH][RCHUNKS][4];        // per-chunk sA,sEA,sB,sEB
__device__ float g_dom[BATCH];
__device__ int   g_ctr = 0;                      // reduce completion counter

// ---------------- f32x2 helpers (sm_100+ packed fp32) ----------------
__device__ __forceinline__ unsigned long long pack2(float lo, float hi) {
    unsigned long long r;
    asm("mov.b64 %0, {%1, %2};" : "=l"(r) : "f"(lo), "f"(hi));
    return r;
}
__device__ __forceinline__ unsigned long long fma2(unsigned long long a,
                                                   unsigned long long b,
                                                   unsigned long long c) {
    unsigned long long r;
    asm("fma.rn.f32x2 %0, %1, %2, %3;" : "=l"(r) : "l"(a), "l"(b), "l"(c));
    return r;
}
__device__ __forceinline__ float2 unpack2(unsigned long long v) {
    float2 f;
    asm("mov.b64 {%0, %1}, %2;" : "=f"(f.x), "=f"(f.y) : "l"(v));
    return f;
}

// Shared for the chamfer path: double-buffered packed key tiles.
// Float layout of each buffer (aliased as ulonglong2[64]):
//   sA: [j*4+0,1] = {-2x_{2j}, -2x_{2j+1}}, [j*4+2,3] = {-2y pair}
//   sB: [j*4+0,1] = {-2z pair},             [j*4+2,3] = {|k|^2 pair}
__shared__ float sA[2][KTILE * 2];
__shared__ float sB[2][KTILE * 2];

// Shared for the domain path (distinct blocks; fine to coexist).
__shared__ float xs[FDIM];
__shared__ float h1[H1DIM];
__shared__ float h2[H2DIM];
__shared__ float lg[DDIM];

__device__ __forceinline__ void domain_block(
    int b, int tid,
    const float* __restrict__ X,
    const float* __restrict__ W1, const float* __restrict__ b1,
    const float* __restrict__ W2, const float* __restrict__ b2,
    const float* __restrict__ W3, const float* __restrict__ b3,
    const int* __restrict__ labels)
{
    for (int i = tid; i < FDIM; i += TPB) xs[i] = X[b * FDIM + i];
    __syncthreads();

    // layer 1: 128 threads x 2 outputs
    {
        float a0 = b1[tid], a1 = b1[tid + 128];
        #pragma unroll 8
        for (int f = 0; f < FDIM; f++) {
            float x = xs[f];
            a0 = fmaf(x, W1[f * H1DIM + tid],       a0);
            a1 = fmaf(x, W1[f * H1DIM + tid + 128], a1);
        }
        h1[tid]       = fmaxf(a0, 0.0f);
        h1[tid + 128] = fmaxf(a1, 0.0f);
    }
    __syncthreads();
    // layer 2: 128 threads x 1 output
    {
        float a = b2[tid];
        #pragma unroll 8
        for (int k = 0; k < H1DIM; k++)
            a = fmaf(h1[k], W2[k * H2DIM + tid], a);
        h2[tid] = fmaxf(a, 0.0f);
    }
    __syncthreads();
    if (tid < DDIM) {
        float a = b3[tid];
        #pragma unroll 8
        for (int k = 0; k < H2DIM; k++)
            a = fmaf(h2[k], W3[k * DDIM + tid], a);
        lg[tid] = a;
    }
    __syncthreads();
    if (tid == 0) {
        float mx = lg[0];
        for (int d = 1; d < DDIM; d++) mx = fmaxf(mx, lg[d]);
        float se = 0.f;
        for (int d = 0; d < DDIM; d++) se += expf(lg[d] - mx);
        g_dom[b] = (mx + logf(se)) - lg[labels[b]];
    }
}

// blockIdx.y < 2*KSPLIT : chamfer (dir = y&1, split = y>>1)
// blockIdx.y == 2*KSPLIT: domain MLP for batch z (x==0 only) — runs
//                         concurrently, fully hidden under chamfer.
__global__ __launch_bounds__(TPB) void main_kernel(
    const float* __restrict__ P, const float* __restrict__ T,
    const float* __restrict__ X,
    const float* __restrict__ W1, const float* __restrict__ b1,
    const float* __restrict__ W2, const float* __restrict__ b2,
    const float* __restrict__ W3, const float* __restrict__ b3,
    const int* __restrict__ labels)
{
    const int tid = threadIdx.x;
    const int b   = blockIdx.z;

    if (blockIdx.y == 2 * KSPLIT) {
        if (blockIdx.x == 0)
            domain_block(b, tid, X, W1, b1, W2, b2, W3, b3, labels);
        return;
    }

    const int dir   = blockIdx.y & 1;
    const int split = blockIdx.y >> 1;
    const int qb    = blockIdx.x;
    const int k0    = split * KCHUNK;

    const float* Q = dir ? (T + (size_t)b * NP * 3) : (P + (size_t)b * NP * 3);
    const float* K = dir ? (P + (size_t)b * NP * 3) : (T + (size_t)b * NP * 3);

    unsigned long long qxd[PPT], qyd[PPT], qzd[PPT];
    float q2[PPT], emin[PPT];
    #pragma unroll
    for (int p = 0; p < PPT; p++) {
        int q = qb * QTILE + p * TPB + tid;
        float qx = Q[q * 3 + 0];
        float qy = Q[q * 3 + 1];
        float qz = Q[q * 3 + 2];
        qxd[p] = pack2(qx, qx);
        qyd[p] = pack2(qy, qy);
        qzd[p] = pack2(qz, qz);
        q2[p]  = qx * qx + qy * qy + qz * qz;
        emin[p] = __int_as_float(0x7f800000);
    }

    // Packed store offsets for this thread's key (one key per thread).
    const int jo = (tid >> 1) * 4 + (tid & 1);

    // Prologue: load + store tile 0.
    float kx = K[(k0 + tid) * 3 + 0];
    float ky = K[(k0 + tid) * 3 + 1];
    float kz = K[(k0 + tid) * 3 + 2];
    sA[0][jo]     = -2.0f * kx;
    sA[0][jo + 2] = -2.0f * ky;
    sB[0][jo]     = -2.0f * kz;
    sB[0][jo + 2] = kx * kx + ky * ky + kz * kz;
    __syncthreads();

    for (int t = 0; t < NTILES; t++) {
        const int buf = t & 1;
        // Prefetch next tile into registers (latency hidden by compute below).
        if (t + 1 < NTILES) {
            int k = k0 + (t + 1) * KTILE + tid;
            kx = K[k * 3 + 0];
            ky = K[k * 3 + 1];
            kz = K[k * 3 + 2];
        }

        const ulonglong2* pA = (const ulonglong2*)sA[buf];
        const ulonglong2* pB = (const ulonglong2*)sB[buf];
        #pragma unroll 8
        for (int j = 0; j < KTILE / 2; j++) {
            ulonglong2 A = pA[j];   // LDS.128 warp-uniform broadcast
            ulonglong2 B = pB[j];   // LDS.128
            #pragma unroll
            for (int p = 0; p < PPT; p++) {
                unsigned long long e = fma2(qxd[p], A.x, B.y);
                e = fma2(qyd[p], A.y, e);
                e = fma2(qzd[p], B.x, e);
                float2 ef = unpack2(e);
                emin[p] = fminf(emin[p], fminf(ef.x, ef.y));
            }
        }

        if (t + 1 < NTILES) {
            const int nbuf = buf ^ 1;   // last used at t-1; all warps are past it
            sA[nbuf][jo]     = -2.0f * kx;
            sA[nbuf][jo + 2] = -2.0f * ky;
            sB[nbuf][jo]     = -2.0f * kz;
            sB[nbuf][jo + 2] = kx * kx + ky * ky + kz * kz;
        }
        __syncthreads();
    }

    #pragma unroll
    for (int p = 0; p < PPT; p++) {
        int q = qb * QTILE + p * TPB + tid;   // coalesced unique store
        g_pmin[dir][b][split][q] = emin[p] + q2[p];
    }
}

// Min over KSPLIT partials -> per-chunk sums; the LAST finishing block also
// performs the final combine (no extra launch).
__global__ __launch_bounds__(256) void reduce_combine_kernel(
    const float* __restrict__ dsw, float* __restrict__ out)
{
    const int b   = blockIdx.y;
    const int tid = threadIdx.x;
    const int q0  = blockIdx.x * 1024 + tid * 4;

    float sums[4];   // sA, sEA, sB, sEB
    #pragma unroll
    for (int dir = 0; dir < 2; dir++) {
        const float4* s0 = (const float4*)&g_pmin[dir][b][0][q0];
        const float4* s1 = (const float4*)&g_pmin[dir][b][1][q0];
        const float4* s2 = (const float4*)&g_pmin[dir][b][2][q0];
        const float4* s3 = (const float4*)&g_pmin[dir][b][3][q0];
        float4 a = *s0, c = *s1, d = *s2, e = *s3;
        float m0 = fminf(fminf(a.x, c.x), fminf(d.x, e.x));
        float m1 = fminf(fminf(a.y, c.y), fminf(d.y, e.y));
        float m2 = fminf(fminf(a.z, c.z), fminf(d.z, e.z));
        float m3 = fminf(fminf(a.w, c.w), fminf(d.w, e.w));
        sums[dir * 2 + 0] = m0 + m1 + m2 + m3;
        sums[dir * 2 + 1] = __expf(-m0 * INV_C) + __expf(-m1 * INV_C)
                          + __expf(-m2 * INV_C) + __expf(-m3 * INV_C);
    }

    #pragma unroll
    for (int s = 16; s > 0; s >>= 1) {
        #pragma unroll
        for (int i = 0; i < 4; i++)
            sums[i] += __shfl_xor_sync(0xffffffffu, sums[i], s);
    }

    __shared__ float red[8][4];
    __shared__ int   last;
    int w = tid >> 5;
    if ((tid & 31) == 0) {
        red[w][0] = sums[0]; red[w][1] = sums[1];
        red[w][2] = sums[2]; red[w][3] = sums[3];
    }
    __syncthreads();
    if (tid < 4) {
        float acc = 0.f;
        #pragma unroll
        for (int ww = 0; ww < 8; ww++) acc += red[ww][tid];
        g_r2[b][blockIdx.x][tid] = acc;
    }
    // completion counter: last block does the combine
    if (tid == 0) {
        __threadfence();
        int old = atomicAdd(&g_ctr, 1);
        last = (old == RCHUNKS * BATCH - 1) ? 1 : 0;
    }
    __syncthreads();
    if (!last) return;
    if (tid == 0) atomicExch(&g_ctr, 0);   // reset for graph replay

    if (tid < 32) {
        const int t = tid;
        float sA = 0.f, sEA = 0.f, sB = 0.f, sEB = 0.f;
        float dwc = 0.f, domc = 0.f;
        if (t < BATCH) {
            #pragma unroll
            for (int c = 0; c < RCHUNKS; c++) {
                sA  += g_r2[t][c][0];
                sEA += g_r2[t][c][1];
                sB  += g_r2[t][c][2];
                sEB += g_r2[t][c][3];
            }
            const float invN = 1.0f / (float)NP;
            float ch_i = sA * invN + sB * invN;
            float p_i  = sEA * invN;
            float r_i  = sEB * invN;
            float f_i  = 2.0f * p_i * r_i / (p_i + r_i + 1e-8f);
            float loss_i = ch_i + FSCORE_W * (1.0f - f_i);
            dwc  = dsw[t] * loss_i;
            domc = g_dom[t];
        }
        #pragma unroll
        for (int s = 16; s > 0; s >>= 1) {
            sA   += __shfl_xor_sync(0xffffffffu, sA,   s);
            sEA  += __shfl_xor_sync(0xffffffffu, sEA,  s);
            sB   += __shfl_xor_sync(0xffffffffu, sB,   s);
            sEB  += __shfl_xor_sync(0xffffffffu, sEB,  s);
            dwc  += __shfl_xor_sync(0xffffffffu, dwc,  s);
            domc += __shfl_xor_sync(0xffffffffu, domc, s);
        }
        if (t == 0) {
            const float invBN = 1.0f / (float)(BATCH * NP);
            float chamfer = sA * invBN + sB * invBN;
            float prec = sEA * invBN;
            float rec  = sEB * invBN;
            float fscore = 2.0f * prec * rec / (prec + rec + 1e-8f);
            float task = chamfer + FSCORE_W * (1.0f - fscore);
            out[0] = TASK_W * task + DOMAIN_W * (domc / (float)BATCH)
                   + (dwc / (float)BATCH);
        }
    }
}

extern "C" void kernel_launch(void* const* d_in, const int* in_sizes, int n_in,
                              void* d_out, int out_size)
{
    const float* pred_pc   = (const float*)d_in[0];
    const float* target_pc = (const float*)d_in[1];
    const float* dfeat     = (const float*)d_in[2];
    const float* dsw       = (const float*)d_in[3];
    const float* W1 = (const float*)d_in[4];
    const float* b1 = (const float*)d_in[5];
    const float* W2 = (const float*)d_in[6];
    const float* b2 = (const float*)d_in[7];
    const float* W3 = (const float*)d_in[8];
    const float* b3 = (const float*)d_in[9];
    const int*   labels = (const int*)d_in[10];
    float* out = (float*)d_out;

    // (8, 9, 8): y<8 chamfer split/dir blocks; y==8,x==0 domain blocks.
    dim3 grid(QB, 2 * KSPLIT + 1, BATCH);
    main_kernel<<<grid, TPB>>>(pred_pc, target_pc, dfeat,
                               W1, b1, W2, b2, W3, b3, labels);

    dim3 rgrid(RCHUNKS, BATCH);
    reduce_combine_kernel<<<rgrid, 256>>>(dsw, out);
}

// round 7
// speedup vs baseline: 1.9631x; 1.0339x over previous
#include <cuda_runtime.h>
#include <math.h>

// Problem constants (fixed by the dataset instance)
#define BATCH   8
#define NP      4096
#define FDIM    512
#define H1DIM   256
#define H2DIM   128
#define DDIM    6

#define FSCORE_W 0.1f
#define TASK_W   1.0f
#define DOMAIN_W 0.1f
#define INV_C    5000.0f       // 1/(2*sigma^2)

// Chamfer tiling
#define TPB     128
#define PPT     4
#define QTILE   (TPB*PPT)      // 512 queries per block
#define QB      (NP/QTILE)     // 8
#define KSPLIT  4
#define KCHUNK  (NP/KSPLIT)    // 1024 keys per block
#define KTILE   128            // keys per shared tile
#define NTILES  (KCHUNK/KTILE) // 8

#define NGROUPS (2*BATCH*QB)           // 128 chamfer groups
#define NARRIVE (NGROUPS + BATCH)      // + 8 domain blocks = 136

// Scratch (device globals; data slots written unconditionally each launch).
__device__ float g_pmin[2][BATCH][KSPLIT][NP];  // per-split partial mins
__device__ float g_r3[2][BATCH][QB][2];         // per-group (sum_d, sum_exp)
__device__ float g_dom[BATCH];
__device__ int   g_ctr_q[2][BATCH][QB];         // zero-init; self-resetting
__device__ int   g_ctr = 0;                     // zero-init; self-resetting

// ---------------- f32x2 helpers (sm_100+ packed fp32) ----------------
__device__ __forceinline__ unsigned long long pack2(float lo, float hi) {
    unsigned long long r;
    asm("mov.b64 %0, {%1, %2};" : "=l"(r) : "f"(lo), "f"(hi));
    return r;
}
__device__ __forceinline__ unsigned long long fma2(unsigned long long a,
                                                   unsigned long long b,
                                                   unsigned long long c) {
    unsigned long long r;
    asm("fma.rn.f32x2 %0, %1, %2, %3;" : "=l"(r) : "l"(a), "l"(b), "l"(c));
    return r;
}
__device__ __forceinline__ float2 unpack2(unsigned long long v) {
    float2 f;
    asm("mov.b64 {%0, %1}, %2;" : "=f"(f.x), "=f"(f.y) : "l"(v));
    return f;
}

// Shared: double-buffered packed key tiles (chamfer path).
__shared__ float sA[2][KTILE * 2];
__shared__ float sB[2][KTILE * 2];
// Shared: domain path (distinct blocks).
__shared__ float xs[FDIM];
__shared__ float h1[H1DIM];
__shared__ float h2[H2DIM];
__shared__ float lg[DDIM];
// Shared: epilogue flags/reductions.
__shared__ float red2[4][2];
__shared__ int   sh_last, sh_final;

// Final combine (32 threads of whichever block arrives last).
__device__ __forceinline__ void final_combine(
    const float* __restrict__ dsw, float* __restrict__ out, int t)
{
    float sA_ = 0.f, sEA = 0.f, sB_ = 0.f, sEB = 0.f;
    float dwc = 0.f, domc = 0.f;
    if (t < BATCH) {
        #pragma unroll
        for (int qb = 0; qb < QB; qb++) {
            sA_ += g_r3[0][t][qb][0];
            sEA += g_r3[0][t][qb][1];
            sB_ += g_r3[1][t][qb][0];
            sEB += g_r3[1][t][qb][1];
        }
        const float invN = 1.0f / (float)NP;
        float ch_i = sA_ * invN + sB_ * invN;
        float p_i  = sEA * invN;
        float r_i  = sEB * invN;
        float f_i  = 2.0f * p_i * r_i / (p_i + r_i + 1e-8f);
        float loss_i = ch_i + FSCORE_W * (1.0f - f_i);
        dwc  = dsw[t] * loss_i;
        domc = g_dom[t];
    }
    #pragma unroll
    for (int s = 16; s > 0; s >>= 1) {
        sA_  += __shfl_xor_sync(0xffffffffu, sA_,  s);
        sEA  += __shfl_xor_sync(0xffffffffu, sEA,  s);
        sB_  += __shfl_xor_sync(0xffffffffu, sB_,  s);
        sEB  += __shfl_xor_sync(0xffffffffu, sEB,  s);
        dwc  += __shfl_xor_sync(0xffffffffu, dwc,  s);
        domc += __shfl_xor_sync(0xffffffffu, domc, s);
    }
    if (t == 0) {
        const float invBN = 1.0f / (float)(BATCH * NP);
        float chamfer = sA_ * invBN + sB_ * invBN;
        float prec = sEA * invBN;
        float rec  = sEB * invBN;
        float fscore = 2.0f * prec * rec / (prec + rec + 1e-8f);
        float task = chamfer + FSCORE_W * (1.0f - fscore);
        out[0] = TASK_W * task + DOMAIN_W * (domc / (float)BATCH)
               + (dwc / (float)BATCH);
    }
}

// Arrive on the global counter; last arriver (of NARRIVE) runs the combine.
__device__ __forceinline__ void global_arrive(
    const float* __restrict__ dsw, float* __restrict__ out, int tid)
{
    __threadfence();
    if (tid == 0) {
        int old = atomicAdd(&g_ctr, 1);
        sh_final = (old == NARRIVE - 1) ? 1 : 0;
        if (sh_final) atomicExch(&g_ctr, 0);   // reset for graph replay
    }
    __syncthreads();
    if (sh_final && tid < 32) final_combine(dsw, out, tid);
}

__device__ __forceinline__ void domain_block(
    int b, int tid,
    const float* __restrict__ X,
    const float* __restrict__ W1, const float* __restrict__ b1,
    const float* __restrict__ W2, const float* __restrict__ b2,
    const float* __restrict__ W3, const float* __restrict__ b3,
    const int* __restrict__ labels)
{
    for (int i = tid; i < FDIM; i += TPB) xs[i] = X[b * FDIM + i];
    __syncthreads();
    {   // layer 1: 128 threads x 2 outputs
        float a0 = b1[tid], a1 = b1[tid + 128];
        #pragma unroll 8
        for (int f = 0; f < FDIM; f++) {
            float x = xs[f];
            a0 = fmaf(x, W1[f * H1DIM + tid],       a0);
            a1 = fmaf(x, W1[f * H1DIM + tid + 128], a1);
        }
        h1[tid]       = fmaxf(a0, 0.0f);
        h1[tid + 128] = fmaxf(a1, 0.0f);
    }
    __syncthreads();
    {   // layer 2
        float a = b2[tid];
        #pragma unroll 8
        for (int k = 0; k < H1DIM; k++)
            a = fmaf(h1[k], W2[k * H2DIM + tid], a);
        h2[tid] = fmaxf(a, 0.0f);
    }
    __syncthreads();
    if (tid < DDIM) {
        float a = b3[tid];
        #pragma unroll 8
        for (int k = 0; k < H2DIM; k++)
            a = fmaf(h2[k], W3[k * DDIM + tid], a);
        lg[tid] = a;
    }
    __syncthreads();
    if (tid == 0) {
        float mx = lg[0];
        for (int d = 1; d < DDIM; d++) mx = fmaxf(mx, lg[d]);
        float se = 0.f;
        for (int d = 0; d < DDIM; d++) se += expf(lg[d] - mx);
        g_dom[b] = (mx + logf(se)) - lg[labels[b]];
    }
    __syncthreads();
}

// Single launch: chamfer (y<8), domain MLP (y==8, x==0). Reduction and the
// final combine happen in-kernel via completion counters.
__global__ __launch_bounds__(TPB) void main_kernel(
    const float* __restrict__ P, const float* __restrict__ T,
    const float* __restrict__ X,
    const float* __restrict__ W1, const float* __restrict__ b1,
    const float* __restrict__ W2, const float* __restrict__ b2,
    const float* __restrict__ W3, const float* __restrict__ b3,
    const int* __restrict__ labels,
    const float* __restrict__ dsw, float* __restrict__ out)
{
    const int tid = threadIdx.x;
    const int b   = blockIdx.z;

    if (blockIdx.y == 2 * KSPLIT) {
        if (blockIdx.x == 0) {
            domain_block(b, tid, X, W1, b1, W2, b2, W3, b3, labels);
            global_arrive(dsw, out, tid);
        }
        return;
    }

    const int dir   = blockIdx.y & 1;
    const int split = blockIdx.y >> 1;
    const int qb    = blockIdx.x;
    const int k0    = split * KCHUNK;

    const float* Q = dir ? (T + (size_t)b * NP * 3) : (P + (size_t)b * NP * 3);
    const float* K = dir ? (P + (size_t)b * NP * 3) : (T + (size_t)b * NP * 3);

    unsigned long long qxd[PPT], qyd[PPT], qzd[PPT];
    float q2[PPT], emin[PPT];
    #pragma unroll
    for (int p = 0; p < PPT; p++) {
        int q = qb * QTILE + p * TPB + tid;
        float qx = Q[q * 3 + 0];
        float qy = Q[q * 3 + 1];
        float qz = Q[q * 3 + 2];
        qxd[p] = pack2(qx, qx);
        qyd[p] = pack2(qy, qy);
        qzd[p] = pack2(qz, qz);
        q2[p]  = qx * qx + qy * qy + qz * qz;
        emin[p] = __int_as_float(0x7f800000);
    }

    const int jo = (tid >> 1) * 4 + (tid & 1);   // packed store offset

    // Prologue: tile 0.
    float kx = K[(k0 + tid) * 3 + 0];
    float ky = K[(k0 + tid) * 3 + 1];
    float kz = K[(k0 + tid) * 3 + 2];
    sA[0][jo]     = -2.0f * kx;
    sA[0][jo + 2] = -2.0f * ky;
    sB[0][jo]     = -2.0f * kz;
    sB[0][jo + 2] = kx * kx + ky * ky + kz * kz;
    __syncthreads();

    for (int t = 0; t < NTILES; t++) {
        const int buf = t & 1;
        if (t + 1 < NTILES) {
            int k = k0 + (t + 1) * KTILE + tid;
            kx = K[k * 3 + 0];
            ky = K[k * 3 + 1];
            kz = K[k * 3 + 2];
        }

        const ulonglong2* pA = (const ulonglong2*)sA[buf];
        const ulonglong2* pB = (const ulonglong2*)sB[buf];
        #pragma unroll 8
        for (int j = 0; j < KTILE / 2; j++) {
            ulonglong2 A = pA[j];   // LDS.128 warp-uniform broadcast
            ulonglong2 B = pB[j];
            #pragma unroll
            for (int p = 0; p < PPT; p++) {
                unsigned long long e = fma2(qxd[p], A.x, B.y);
                e = fma2(qyd[p], A.y, e);
                e = fma2(qzd[p], B.x, e);
                float2 ef = unpack2(e);
                emin[p] = fminf(emin[p], fminf(ef.x, ef.y));
            }
        }

        if (t + 1 < NTILES) {
            const int nbuf = buf ^ 1;
            sA[nbuf][jo]     = -2.0f * kx;
            sA[nbuf][jo + 2] = -2.0f * ky;
            sB[nbuf][jo]     = -2.0f * kz;
            sB[nbuf][jo + 2] = kx * kx + ky * ky + kz * kz;
        }
        __syncthreads();
    }

    #pragma unroll
    for (int p = 0; p < PPT; p++) {
        int q = qb * QTILE + p * TPB + tid;   // coalesced unique store
        g_pmin[dir][b][split][q] = emin[p] + q2[p];
    }

    // ---- group arrive: last of the KSPLIT blocks reduces this q-range ----
    __threadfence();
    if (tid == 0) {
        int old = atomicAdd(&g_ctr_q[dir][b][qb], 1);
        sh_last = (old == KSPLIT - 1) ? 1 : 0;
        if (sh_last) g_ctr_q[dir][b][qb] = 0;   // reset for graph replay
    }
    __syncthreads();
    if (!sh_last) return;

    {
        const int q0 = qb * QTILE + tid * 4;
        const float4 a = *(const float4*)&g_pmin[dir][b][0][q0];
        const float4 c = *(const float4*)&g_pmin[dir][b][1][q0];
        const float4 d = *(const float4*)&g_pmin[dir][b][2][q0];
        const float4 e = *(const float4*)&g_pmin[dir][b][3][q0];
        float m0 = fminf(fminf(a.x, c.x), fminf(d.x, e.x));
        float m1 = fminf(fminf(a.y, c.y), fminf(d.y, e.y));
        float m2 = fminf(fminf(a.z, c.z), fminf(d.z, e.z));
        float m3 = fminf(fminf(a.w, c.w), fminf(d.w, e.w));
        float sd = m0 + m1 + m2 + m3;
        float se = __expf(-m0 * INV_C) + __expf(-m1 * INV_C)
                 + __expf(-m2 * INV_C) + __expf(-m3 * INV_C);
        #pragma unroll
        for (int s = 16; s > 0; s >>= 1) {
            sd += __shfl_xor_sync(0xffffffffu, sd, s);
            se += __shfl_xor_sync(0xffffffffu, se, s);
        }
        int w = tid >> 5;
        if ((tid & 31) == 0) { red2[w][0] = sd; red2[w][1] = se; }
        __syncthreads();
        if (tid == 0) {
            g_r3[dir][b][qb][0] = red2[0][0] + red2[1][0] + red2[2][0] + red2[3][0];
            g_r3[dir][b][qb][1] = red2[0][1] + red2[1][1] + red2[2][1] + red2[3][1];
        }
    }

    global_arrive(dsw, out, tid);
}

extern "C" void kernel_launch(void* const* d_in, const int* in_sizes, int n_in,
                              void* d_out, int out_size)
{
    const float* pred_pc   = (const float*)d_in[0];
    const float* target_pc = (const float*)d_in[1];
    const float* dfeat     = (const float*)d_in[2];
    const float* dsw       = (const float*)d_in[3];
    const float* W1 = (const float*)d_in[4];
    const float* b1 = (const float*)d_in[5];
    const float* W2 = (const float*)d_in[6];
    const float* b2 = (const float*)d_in[7];
    const float* W3 = (const float*)d_in[8];
    const float* b3 = (const float*)d_in[9];
    const int*   labels = (const int*)d_in[10];
    float* out = (float*)d_out;

    // (8, 9, 8): y<8 chamfer split/dir blocks; y==8,x==0 domain blocks.
    dim3 grid(QB, 2 * KSPLIT + 1, BATCH);
    main_kernel<<<grid, TPB>>>(pred_pc, target_pc, dfeat,
                               W1, b1, W2, b2, W3, b3, labels, dsw, out);
}